// round 15
// baseline (speedup 1.0000x reference)
#include <cuda_runtime.h>
#include <cuda_bf16.h>
#include <cstdint>

#define NVOX 100000
#define MFINE 400000

__device__ __forceinline__ float relu_(float x){ return fmaxf(x, 0.0f); }

// ---------------- smem / mma.sync helpers (plain sm_80+ PTX) ----------------
__device__ __forceinline__ uint32_t smem_u32(const void* p){
  uint32_t a;
  asm("{ .reg .u64 t; cvta.to.shared.u64 t, %1; cvt.u32.u64 %0, t; }" : "=r"(a) : "l"(p));
  return a;
}
__device__ __forceinline__ void sts128(uint32_t a, uint4 v){
  asm volatile("st.shared.v4.b32 [%0], {%1,%2,%3,%4};"
               :: "r"(a), "r"(v.x), "r"(v.y), "r"(v.z), "r"(v.w) : "memory");
}
__device__ __forceinline__ void sts32(uint32_t a, uint32_t v){
  asm volatile("st.shared.b32 [%0], %1;" :: "r"(a), "r"(v) : "memory");
}
__device__ __forceinline__ uint32_t SWZ(uint32_t o){ return o ^ ((o >> 3) & 0x70u); }

__device__ __forceinline__ void cpasync16(uint32_t dst, const void* src){
  asm volatile("cp.async.cg.shared.global [%0], [%1], 16;" :: "r"(dst), "l"(src) : "memory");
}
#define CP_COMMIT()  asm volatile("cp.async.commit_group;" ::: "memory")
#define CP_WAIT(n)   asm volatile("cp.async.wait_group %0;" :: "n"(n) : "memory")

__device__ __forceinline__ void ldmx4(uint32_t* r, uint32_t a){
  asm volatile("ldmatrix.sync.aligned.m8n8.x4.shared.b16 {%0,%1,%2,%3}, [%4];"
               : "=r"(r[0]), "=r"(r[1]), "=r"(r[2]), "=r"(r[3]) : "r"(a));
}
__device__ __forceinline__ void ldmx2(uint32_t* r, uint32_t a){
  asm volatile("ldmatrix.sync.aligned.m8n8.x2.shared.b16 {%0,%1}, [%2];"
               : "=r"(r[0]), "=r"(r[1]) : "r"(a));
}
__device__ __forceinline__ void mma16816(float* d, const uint32_t* a, const uint32_t* b){
  asm volatile("mma.sync.aligned.m16n8k16.row.col.f32.bf16.bf16.f32 "
               "{%0,%1,%2,%3},{%4,%5,%6,%7},{%8,%9},{%0,%1,%2,%3};"
               : "+f"(d[0]), "+f"(d[1]), "+f"(d[2]), "+f"(d[3])
               : "r"(a[0]), "r"(a[1]), "r"(a[2]), "r"(a[3]), "r"(b[0]), "r"(b[1]));
}
__device__ __forceinline__ uint32_t packbf(float x, float y){
  __nv_bfloat162 p;
  p.x = __float2bfloat16(x);
  p.y = __float2bfloat16(y);
  return *reinterpret_cast<uint32_t*>(&p);
}

// ---------------- scratch (static device memory; no allocations) ----------------
__device__ uint4 g_fa[(size_t)NVOX*8];                  // bf16 feature ping buffer, 128B/row
__device__ uint4 g_fb[(size_t)NVOX*8];                  // bf16 feature pong buffer
__device__ uint4 g_Whi[3*13824];                        // [L][k][co][ci] bf16 (ci padded to 64)
__device__ uint4 g_WtT[8*512];                          // tconv weights [k][co][ci] bf16
__device__ uint4 g_Wd1T[512];                           // d1 weights [co][ci] bf16
__device__ uint4 g_Wd2T[256];                           // d2 weights [co(32)][ci(64)] bf16
__device__ __align__(16) unsigned char g_zero[128];     // zero row for invalid neighbors
__device__ int   g_nbrT[27*NVOX];                       // transposed rulebook [k][v]
__device__ int   g_list[MFINE + 512];
__device__ int   g_cnt[8*64];
__device__ int   g_cursor[8*64];

// ---------------- bucketing kernels (unchanged, known-good) ----------
__global__ void init_kernel(){
  int i = blockIdx.x*256 + threadIdx.x;
  if (i < MFINE + 512) g_list[i] = -1;
  if (i < 8) g_cnt[i*64] = 0;
}
__global__ void count_kernel(const int* __restrict__ off){
  __shared__ int c[8];
  int t = threadIdx.x;
  if (t < 8) c[t] = 0;
  __syncthreads();
  int m = blockIdx.x*256 + t;
  if (m < MFINE) atomicAdd(&c[off[m]], 1);
  __syncthreads();
  if (t < 8) atomicAdd(&g_cnt[t*64], c[t]);
}
__global__ void scan_kernel(){
  int base = 0;
  for (int k = 0; k < 8; ++k){
    g_cursor[k*64] = base;
    base += ((g_cnt[k*64] + 63) >> 6) << 6;
  }
}
__global__ void scatter_kernel(const int* __restrict__ off){
  __shared__ int c[8], sb[8];
  int t = threadIdx.x;
  if (t < 8) c[t] = 0;
  __syncthreads();
  int m = blockIdx.x*256 + t;
  int k = 0, lp = 0;
  if (m < MFINE){ k = off[m]; lp = atomicAdd(&c[k], 1); }
  __syncthreads();
  if (t < 8) sb[t] = atomicAdd(&g_cursor[t*64], c[t]);
  __syncthreads();
  if (m < MFINE) g_list[sb[k] + lp] = m;
}

// ---------------- prep kernels ----------------
__global__ void cvt_feats_kernel(const float* __restrict__ x){
  int t = blockIdx.x*256 + threadIdx.x;
  if (t >= NVOX*64) return;
  int v = t >> 6, c = t & 63;
  float val = (c < 32) ? x[(size_t)v*32 + c] : 0.0f;
  reinterpret_cast<__nv_bfloat16*>(g_fa)[t] = __float2bfloat16(val);
}
// conv weights: [k][ci][co] fp32 -> [k][co][ci(64, zero-padded)] bf16
template<int CIN, int L>
__global__ void prep_w_kernel(const float* __restrict__ W){
  int t = blockIdx.x*256 + threadIdx.x;
  if (t >= 27*64*64) return;
  int k = t >> 12, co = (t >> 6) & 63, ci = t & 63;
  float val = (ci < CIN) ? W[((size_t)k*CIN + ci)*64 + co] : 0.0f;
  reinterpret_cast<__nv_bfloat16*>(g_Whi)[(size_t)L*110592 + t] = __float2bfloat16(val);
}
// fine weights: transpose to [co][ci] bf16
__global__ void prep_wfine_kernel(const float* __restrict__ Wt,
                                  const float* __restrict__ Wd1,
                                  const float* __restrict__ Wd2){
  int t = blockIdx.x*256 + threadIdx.x;
  if (t < 8*64*64){
    int k = t >> 12, co = (t >> 6) & 63, ci = t & 63;
    reinterpret_cast<__nv_bfloat16*>(g_WtT)[t] =
        __float2bfloat16(Wt[(size_t)k*4096 + ci*64 + co]);
  } else if (t < 8*64*64 + 64*64){
    int u = t - 8*64*64; int co = u >> 6, ci = u & 63;
    reinterpret_cast<__nv_bfloat16*>(g_Wd1T)[u] = __float2bfloat16(Wd1[ci*64 + co]);
  } else if (t < 8*64*64 + 64*64 + 32*64){
    int u = t - (8*64*64 + 64*64); int co = u >> 6, ci = u & 63;
    reinterpret_cast<__nv_bfloat16*>(g_Wd2T)[u] = __float2bfloat16(Wd2[ci*32 + co]);
  }
}
__global__ void trans_nbr_kernel(const int* __restrict__ nbr){
  int t = blockIdx.x*256 + threadIdx.x;
  if (t >= 27*NVOX) return;
  int k = t / NVOX, v = t - k*NVOX;
  g_nbrT[t] = nbr[(size_t)v*27 + k];
}

// ---------------- mma-based sparse 3x3x3 conv, cp.async double-buffered ----------------
// block: 128 voxels x 64 co, 4 warps; warp = M32 x N64 via m16n8k16 bf16 MMA.
// SRC: 0 = read g_fa (write g_fb), 1 = read g_fb (write g_fa). Always writes bf16.
template<int L, int SRC>
__global__ __launch_bounds__(128) void conv_mma_kernel(const float* __restrict__ b, int N)
{
  __shared__ __align__(1024) unsigned char smraw[49152];
  const uint32_t A0 = smem_u32(smraw);                 // A bufs @ 0, 16384
  const uint32_t W0 = A0 + 32768u;                     // W bufs @ 32768, 40960

  const uint4* __restrict__ fh = (SRC == 0) ? g_fa : g_fb;

  const int tid  = threadIdx.x;
  const int wid  = tid >> 5;
  const int lane = tid & 31;
  const int v0   = blockIdx.x * 128;
  const int vg   = v0 + tid;

  constexpr int SMAX = (L == 0) ? 2 : 4;
  constexpr int JMAX = (L == 0) ? 4 : 8;

  const uint32_t aRow = (uint32_t)(lane & 15);
  const uint32_t aKb  = (uint32_t)((lane >> 4) * 16);
  const uint32_t bRow = (uint32_t)(lane & 7);
  const uint32_t bKb  = (uint32_t)(((lane >> 3) & 1) * 16);

  const int co = tid >> 1, hh = tid & 1;
  const uint4* wsrc_h = g_Whi + (size_t)L*13824 + (size_t)co*8 + hh*4;
  const uint4* zrow = reinterpret_cast<const uint4*>(g_zero);

  float acc[2][8][4];
  #pragma unroll
  for (int m = 0; m < 2; ++m)
    #pragma unroll
    for (int n = 0; n < 8; ++n)
      #pragma unroll
      for (int q = 0; q < 4; ++q) acc[m][n][q] = 0.0f;

  // prefetch of one k-offset into buffer (kk & 1)
  auto prefetch = [&](int kk){
    const int buf = kk & 1;
    const uint32_t Ab = A0 + (uint32_t)buf*16384u;
    const uint32_t Wb = W0 + (uint32_t)buf*8192u;
    int idx = (vg < N) ? g_nbrT[(size_t)kk*NVOX + vg] : N;
    const uint4* sh = (idx < N) ? (fh + (size_t)idx*8) : zrow;
    const int step = (idx < N) ? 1 : 0;
    #pragma unroll
    for (int j = 0; j < JMAX; ++j)
      cpasync16(Ab + SWZ((uint32_t)(tid*128 + j*16)), sh + j*step);
    const uint4* wh = wsrc_h + (size_t)kk*512;
    #pragma unroll
    for (int j = 0; j < 4; ++j)
      cpasync16(Wb + SWZ((uint32_t)(co*128 + hh*64 + j*16)), wh + j);
    CP_COMMIT();
  };

  prefetch(0);

  for (int kk = 0; kk < 27; ++kk){
    const int buf = kk & 1;
    if (kk < 26){ prefetch(kk + 1); CP_WAIT(1); }
    else        { CP_WAIT(0); }
    __syncthreads();   // staged data visible to all warps

    const uint32_t Ab = A0 + (uint32_t)buf*16384u;
    const uint32_t Wb = W0 + (uint32_t)buf*8192u;
    #pragma unroll
    for (int s = 0; s < SMAX; ++s){
      uint32_t bhf[8][2];
      #pragma unroll
      for (int n = 0; n < 8; ++n){
        uint32_t bo = SWZ((uint32_t)((n*8 + bRow)*128) + bKb + (uint32_t)(s*32));
        ldmx2(bhf[n], Wb + bo);
      }
      #pragma unroll
      for (int m = 0; m < 2; ++m){
        uint32_t ahf[4];
        uint32_t ao = SWZ((uint32_t)((wid*32 + m*16 + aRow)*128) + aKb + (uint32_t)(s*32));
        ldmx4(ahf, Ab + ao);
        #pragma unroll
        for (int n = 0; n < 8; ++n){
          mma16816(acc[m][n], ahf, bhf[n]);
        }
      }
    }
    __syncthreads();   // block-wide compute done before buf is re-staged (kk+2)
  }

  // epilogue: bias + relu -> bf16
  float2 bias_[8];
  #pragma unroll
  for (int n = 0; n < 8; ++n){
    int col = n*8 + (lane & 3)*2;
    bias_[n].x = b[col];
    bias_[n].y = b[col + 1];
  }
  __nv_bfloat162* dsth = reinterpret_cast<__nv_bfloat162*>((SRC == 0) ? g_fb : g_fa);

  #pragma unroll
  for (int m = 0; m < 2; ++m){
    #pragma unroll
    for (int h2 = 0; h2 < 2; ++h2){
      int r = v0 + wid*32 + m*16 + (lane >> 2) + h2*8;
      if (r < N){
        size_t ebase = (size_t)r*32 + (lane & 3);
        #pragma unroll
        for (int n = 0; n < 8; ++n){
          float va = relu_(acc[m][n][h2*2 + 0] + bias_[n].x);
          float vb = relu_(acc[m][n][h2*2 + 1] + bias_[n].y);
          __nv_bfloat162 ph;
          ph.x = __float2bfloat16(va);
          ph.y = __float2bfloat16(vb);
          dsth[ebase + n*4] = ph;
        }
      }
    }
  }
}

// ---------------- fused fine stage on tensor cores (validated R14) ----------------
__global__ __launch_bounds__(128) void fine_mma_kernel(
    const int* __restrict__ parent, const int* __restrict__ off,
    const float* __restrict__ bt, const float* __restrict__ bd1,
    const float* __restrict__ bd2,
    const float* __restrict__ xup, float* __restrict__ out)
{
  __shared__ __align__(1024) unsigned char sGr[8192];
  __shared__ __align__(1024) unsigned char sYr[8192];
  __shared__ __align__(1024) unsigned char sWr[8192];
  const uint32_t sG = smem_u32(sGr);
  const uint32_t sY = smem_u32(sYr);
  const uint32_t sW = smem_u32(sWr);

  const int tid = threadIdx.x, w = tid >> 5, lane = tid & 31;
  const int base = blockIdx.x * 64;
  int m0 = g_list[base];
  if (m0 < 0) return;
  const int k = off[m0];

  const uint4 zz = make_uint4(0,0,0,0);

  {
    int r = tid >> 1, half = tid & 1;
    int m = g_list[base + r];
    const uint4* src = (m >= 0) ? (g_fb + (size_t)parent[m]*8 + half*4) : nullptr;
    #pragma unroll
    for (int j = 0; j < 4; ++j){
      uint32_t o = SWZ((uint32_t)(r*128 + half*64 + j*16));
      sts128(sG + o, src ? src[j] : zz);
    }
  }
  {
    const uint4* ws = g_WtT + (size_t)k*512 + (size_t)(tid>>1)*8 + (tid&1)*4;
    #pragma unroll
    for (int j = 0; j < 4; ++j){
      uint32_t o = SWZ((uint32_t)((tid>>1)*128 + (tid&1)*64 + j*16));
      sts128(sW + o, ws[j]);
    }
  }
  __syncthreads();

  const uint32_t aRow = (uint32_t)(lane & 15);
  const uint32_t aKb  = (uint32_t)((lane >> 4) * 16);
  const uint32_t bRow = (uint32_t)(lane & 7);
  const uint32_t bKb  = (uint32_t)(((lane >> 3) & 1) * 16);

  // ---- stage 1: G @ WtT -> sY (relu + bt, bf16) ----
  {
    float acc[8][4];
    #pragma unroll
    for (int n = 0; n < 8; ++n){ acc[n][0]=0; acc[n][1]=0; acc[n][2]=0; acc[n][3]=0; }
    #pragma unroll
    for (int s = 0; s < 4; ++s){
      uint32_t bhf[8][2];
      #pragma unroll
      for (int n = 0; n < 8; ++n){
        uint32_t bo = SWZ((uint32_t)((n*8 + bRow)*128) + bKb + (uint32_t)(s*32));
        ldmx2(bhf[n], sW + bo);
      }
      uint32_t ahf[4];
      uint32_t ao = SWZ((uint32_t)((w*16 + aRow)*128) + aKb + (uint32_t)(s*32));
      ldmx4(ahf, sG + ao);
      #pragma unroll
      for (int n = 0; n < 8; ++n) mma16816(acc[n], ahf, bhf[n]);
    }
    #pragma unroll
    for (int n = 0; n < 8; ++n){
      int col = n*8 + (lane & 3)*2;
      float bx = bt[col], by = bt[col + 1];
      #pragma unroll
      for (int h2 = 0; h2 < 2; ++h2){
        int r = w*16 + (lane >> 2) + h2*8;
        uint32_t o = SWZ((uint32_t)(r*128 + col*2));
        sts32(sY + o, packbf(relu_(acc[n][h2*2] + bx), relu_(acc[n][h2*2+1] + by)));
      }
    }
  }
  __syncthreads();
  {
    const uint4* ws = g_Wd1T + (size_t)(tid>>1)*8 + (tid&1)*4;
    #pragma unroll
    for (int j = 0; j < 4; ++j){
      uint32_t o = SWZ((uint32_t)((tid>>1)*128 + (tid&1)*64 + j*16));
      sts128(sW + o, ws[j]);
    }
  }
  __syncthreads();

  // ---- stage 2: Y @ Wd1T -> sG (relu + bd1, bf16) ----
  {
    float acc[8][4];
    #pragma unroll
    for (int n = 0; n < 8; ++n){ acc[n][0]=0; acc[n][1]=0; acc[n][2]=0; acc[n][3]=0; }
    #pragma unroll
    for (int s = 0; s < 4; ++s){
      uint32_t bhf[8][2];
      #pragma unroll
      for (int n = 0; n < 8; ++n){
        uint32_t bo = SWZ((uint32_t)((n*8 + bRow)*128) + bKb + (uint32_t)(s*32));
        ldmx2(bhf[n], sW + bo);
      }
      uint32_t ahf[4];
      uint32_t ao = SWZ((uint32_t)((w*16 + aRow)*128) + aKb + (uint32_t)(s*32));
      ldmx4(ahf, sY + ao);
      #pragma unroll
      for (int n = 0; n < 8; ++n) mma16816(acc[n], ahf, bhf[n]);
    }
    __syncthreads();
    #pragma unroll
    for (int n = 0; n < 8; ++n){
      int col = n*8 + (lane & 3)*2;
      float bx = bd1[col], by = bd1[col + 1];
      #pragma unroll
      for (int h2 = 0; h2 < 2; ++h2){
        int r = w*16 + (lane >> 2) + h2*8;
        uint32_t o = SWZ((uint32_t)(r*128 + col*2));
        sts32(sG + o, packbf(relu_(acc[n][h2*2] + bx), relu_(acc[n][h2*2+1] + by)));
      }
    }
  }
  __syncthreads();
  {
    int row = tid >> 2, q = tid & 3;
    const uint4* ws = g_Wd2T + (size_t)row*8 + q*2;
    #pragma unroll
    for (int j = 0; j < 2; ++j){
      uint32_t o = SWZ((uint32_t)(row*128 + q*32 + j*16));
      sts128(sW + o, ws[j]);
    }
  }
  __syncthreads();

  // ---- stage 3: Z @ Wd2T + bd2 + xup -> out (fp32) ----
  {
    float acc[4][4];
    #pragma unroll
    for (int n = 0; n < 4; ++n){ acc[n][0]=0; acc[n][1]=0; acc[n][2]=0; acc[n][3]=0; }
    #pragma unroll
    for (int s = 0; s < 4; ++s){
      uint32_t bhf[4][2];
      #pragma unroll
      for (int n = 0; n < 4; ++n){
        uint32_t bo = SWZ((uint32_t)((n*8 + bRow)*128) + bKb + (uint32_t)(s*32));
        ldmx2(bhf[n], sW + bo);
      }
      uint32_t ahf[4];
      uint32_t ao = SWZ((uint32_t)((w*16 + aRow)*128) + aKb + (uint32_t)(s*32));
      ldmx4(ahf, sG + ao);
      #pragma unroll
      for (int n = 0; n < 4; ++n) mma16816(acc[n], ahf, bhf[n]);
    }
    #pragma unroll
    for (int n = 0; n < 4; ++n){
      int col = n*8 + (lane & 3)*2;
      float bx = bd2[col], by = bd2[col + 1];
      #pragma unroll
      for (int h2 = 0; h2 < 2; ++h2){
        int r = w*16 + (lane >> 2) + h2*8;
        int m = g_list[base + r];
        if (m >= 0){
          float2 up = *reinterpret_cast<const float2*>(xup + (size_t)m*32 + col);
          float2 o;
          o.x = acc[n][h2*2 + 0] + bx + up.x;
          o.y = acc[n][h2*2 + 1] + by + up.y;
          *reinterpret_cast<float2*>(out + (size_t)m*32 + col) = o;
        }
      }
    }
  }
}

// -------------------------------- launch --------------------------------
extern "C" void kernel_launch(void* const* d_in, const int* in_sizes, int n_in,
                              void* d_out, int out_size)
{
  const float* feats  = (const float*)d_in[0];
  const float* xup    = (const float*)d_in[1];
  const int*   nbr    = (const int*)  d_in[2];
  const int*   parent = (const int*)  d_in[3];
  const int*   off    = (const int*)  d_in[4];
  const float* We1 = (const float*)d_in[5];  const float* be1 = (const float*)d_in[6];
  const float* We2 = (const float*)d_in[7];  const float* be2 = (const float*)d_in[8];
  const float* We3 = (const float*)d_in[9];  const float* be3 = (const float*)d_in[10];
  const float* Wt  = (const float*)d_in[11]; const float* bt  = (const float*)d_in[12];
  const float* Wd1 = (const float*)d_in[13]; const float* bd1 = (const float*)d_in[14];
  const float* Wd2 = (const float*)d_in[15]; const float* bd2 = (const float*)d_in[16];
  float* out = (float*)d_out;

  // prep
  const int wblk = (27*64*64 + 255)/256;
  prep_w_kernel<32,0><<<wblk, 256>>>(We1);
  prep_w_kernel<64,1><<<wblk, 256>>>(We2);
  prep_w_kernel<64,2><<<wblk, 256>>>(We3);
  prep_wfine_kernel<<<(8*64*64 + 64*64 + 32*64 + 255)/256, 256>>>(Wt, Wd1, Wd2);
  cvt_feats_kernel<<<(NVOX*64 + 255)/256, 256>>>(feats);
  trans_nbr_kernel<<<(27*NVOX + 255)/256, 256>>>(nbr);

  // bucket fine voxels by tconv offset
  init_kernel   <<<(MFINE + 512 + 255)/256, 256>>>();
  count_kernel  <<<(MFINE + 255)/256, 256>>>(off);
  scan_kernel   <<<1, 1>>>();
  scatter_kernel<<<(MFINE + 255)/256, 256>>>(off);

  // encoder: 3 sparse convs on tensor cores (cp.async double-buffered)
  const int cblocks = (NVOX + 127)/128;
  conv_mma_kernel<0,0><<<cblocks, 128>>>(be1, NVOX);   // g_fa -> g_fb
  conv_mma_kernel<1,1><<<cblocks, 128>>>(be2, NVOX);   // g_fb -> g_fa
  conv_mma_kernel<2,0><<<cblocks, 128>>>(be3, NVOX);   // g_fa -> g_fb (bf16 for fine)

  // fused fine stage on tensor cores
  fine_mma_kernel<<<(MFINE + 512)/64, 128>>>(parent, off, bt, bd1, bd2, xup, out);
}

// round 16
// speedup vs baseline: 25.2449x; 25.2449x over previous
#include <cuda_runtime.h>
#include <cuda_bf16.h>
#include <cstdint>

#define NVOX 100000
#define MFINE 400000

__device__ __forceinline__ float relu_(float x){ return fmaxf(x, 0.0f); }

// ---------------- smem / mma.sync helpers (plain sm_80+ PTX) ----------------
__device__ __forceinline__ uint32_t smem_u32(const void* p){
  uint32_t a;
  asm("{ .reg .u64 t; cvta.to.shared.u64 t, %1; cvt.u32.u64 %0, t; }" : "=r"(a) : "l"(p));
  return a;
}
__device__ __forceinline__ void sts128(uint32_t a, uint4 v){
  asm volatile("st.shared.v4.b32 [%0], {%1,%2,%3,%4};"
               :: "r"(a), "r"(v.x), "r"(v.y), "r"(v.z), "r"(v.w) : "memory");
}
__device__ __forceinline__ void sts32(uint32_t a, uint32_t v){
  asm volatile("st.shared.b32 [%0], %1;" :: "r"(a), "r"(v) : "memory");
}
__device__ __forceinline__ uint32_t SWZ(uint32_t o){ return o ^ ((o >> 3) & 0x70u); }

__device__ __forceinline__ void ldmx4(uint32_t* r, uint32_t a){
  asm volatile("ldmatrix.sync.aligned.m8n8.x4.shared.b16 {%0,%1,%2,%3}, [%4];"
               : "=r"(r[0]), "=r"(r[1]), "=r"(r[2]), "=r"(r[3]) : "r"(a));
}
__device__ __forceinline__ void ldmx2(uint32_t* r, uint32_t a){
  asm volatile("ldmatrix.sync.aligned.m8n8.x2.shared.b16 {%0,%1}, [%2];"
               : "=r"(r[0]), "=r"(r[1]) : "r"(a));
}
__device__ __forceinline__ void mma16816(float* d, const uint32_t* a, const uint32_t* b){
  asm volatile("mma.sync.aligned.m16n8k16.row.col.f32.bf16.bf16.f32 "
               "{%0,%1,%2,%3},{%4,%5,%6,%7},{%8,%9},{%0,%1,%2,%3};"
               : "+f"(d[0]), "+f"(d[1]), "+f"(d[2]), "+f"(d[3])
               : "r"(a[0]), "r"(a[1]), "r"(a[2]), "r"(a[3]), "r"(b[0]), "r"(b[1]));
}
__device__ __forceinline__ uint32_t packbf(float x, float y){
  __nv_bfloat162 p;
  p.x = __float2bfloat16(x);
  p.y = __float2bfloat16(y);
  return *reinterpret_cast<uint32_t*>(&p);
}

// ---------------- scratch (static device memory; no allocations) ----------------
__device__ uint4 g_fa[(size_t)NVOX*8];                  // bf16 feature ping buffer, 128B/row
__device__ uint4 g_fb[(size_t)NVOX*8];                  // bf16 feature pong buffer
__device__ uint4 g_Whi[3*13824];                        // [L][k][co][ci] bf16 (ci padded to 64)
__device__ uint4 g_WtT[8*512];                          // tconv weights [k][co][ci] bf16
__device__ uint4 g_Wd1T[512];                           // d1 weights [co][ci] bf16
__device__ uint4 g_Wd2T[256];                           // d2 weights [co(32)][ci(64)] bf16
__device__ int   g_nbrT[27*NVOX];                       // transposed rulebook [k][v]
__device__ int   g_list[MFINE + 512];
__device__ int   g_cnt[8*64];
__device__ int   g_cursor[8*64];

// ---------------- bucketing kernels (unchanged, known-good) ----------
__global__ void init_kernel(){
  int i = blockIdx.x*256 + threadIdx.x;
  if (i < MFINE + 512) g_list[i] = -1;
  if (i < 8) g_cnt[i*64] = 0;
}
__global__ void count_kernel(const int* __restrict__ off){
  __shared__ int c[8];
  int t = threadIdx.x;
  if (t < 8) c[t] = 0;
  __syncthreads();
  int m = blockIdx.x*256 + t;
  if (m < MFINE) atomicAdd(&c[off[m]], 1);
  __syncthreads();
  if (t < 8) atomicAdd(&g_cnt[t*64], c[t]);
}
__global__ void scan_kernel(){
  int base = 0;
  for (int k = 0; k < 8; ++k){
    g_cursor[k*64] = base;
    base += ((g_cnt[k*64] + 63) >> 6) << 6;
  }
}
__global__ void scatter_kernel(const int* __restrict__ off){
  __shared__ int c[8], sb[8];
  int t = threadIdx.x;
  if (t < 8) c[t] = 0;
  __syncthreads();
  int m = blockIdx.x*256 + t;
  int k = 0, lp = 0;
  if (m < MFINE){ k = off[m]; lp = atomicAdd(&c[k], 1); }
  __syncthreads();
  if (t < 8) sb[t] = atomicAdd(&g_cursor[t*64], c[t]);
  __syncthreads();
  if (m < MFINE) g_list[sb[k] + lp] = m;
}

// ---------------- prep kernels ----------------
__global__ void cvt_feats_kernel(const float* __restrict__ x){
  int t = blockIdx.x*256 + threadIdx.x;
  if (t >= NVOX*64) return;
  int v = t >> 6, c = t & 63;
  float val = (c < 32) ? x[(size_t)v*32 + c] : 0.0f;
  reinterpret_cast<__nv_bfloat16*>(g_fa)[t] = __float2bfloat16(val);
}
// conv weights: [k][ci][co] fp32 -> [k][co][ci(64, zero-padded)] bf16
template<int CIN, int L>
__global__ void prep_w_kernel(const float* __restrict__ W){
  int t = blockIdx.x*256 + threadIdx.x;
  if (t >= 27*64*64) return;
  int k = t >> 12, co = (t >> 6) & 63, ci = t & 63;
  float val = (ci < CIN) ? W[((size_t)k*CIN + ci)*64 + co] : 0.0f;
  reinterpret_cast<__nv_bfloat16*>(g_Whi)[(size_t)L*110592 + t] = __float2bfloat16(val);
}
// fine weights: transpose to [co][ci] bf16
__global__ void prep_wfine_kernel(const float* __restrict__ Wt,
                                  const float* __restrict__ Wd1,
                                  const float* __restrict__ Wd2){
  int t = blockIdx.x*256 + threadIdx.x;
  if (t < 8*64*64){
    int k = t >> 12, co = (t >> 6) & 63, ci = t & 63;
    reinterpret_cast<__nv_bfloat16*>(g_WtT)[t] =
        __float2bfloat16(Wt[(size_t)k*4096 + ci*64 + co]);
  } else if (t < 8*64*64 + 64*64){
    int u = t - 8*64*64; int co = u >> 6, ci = u & 63;
    reinterpret_cast<__nv_bfloat16*>(g_Wd1T)[u] = __float2bfloat16(Wd1[ci*64 + co]);
  } else if (t < 8*64*64 + 64*64 + 32*64){
    int u = t - (8*64*64 + 64*64); int co = u >> 6, ci = u & 63;
    reinterpret_cast<__nv_bfloat16*>(g_Wd2T)[u] = __float2bfloat16(Wd2[ci*32 + co]);
  }
}
__global__ void trans_nbr_kernel(const int* __restrict__ nbr){
  int t = blockIdx.x*256 + threadIdx.x;
  if (t >= 27*NVOX) return;
  int k = t / NVOX, v = t - k*NVOX;
  g_nbrT[t] = nbr[(size_t)v*27 + k];
}

// ---------------- mma-based sparse 3x3x3 conv, register-pipelined gather ----------------
// block: 128 voxels x 64 co, 4 warps; warp = M32 x N64 via m16n8k16 bf16 MMA.
// Software pipeline: LDGs for k+1 issued before compute of k (latency overlapped);
// LDG results consumed at STS of the NEXT iteration (after compute + barrier).
// SRC: 0 = read g_fa (write g_fb), 1 = read g_fb (write g_fa). Always writes bf16.
template<int L, int SRC>
__global__ __launch_bounds__(128) void conv_mma_kernel(const float* __restrict__ b, int N)
{
  __shared__ __align__(1024) unsigned char smraw[24576];
  const uint32_t Ah = smem_u32(smraw);
  const uint32_t Wh = Ah + 16384u;

  const uint4* __restrict__ fh = (SRC == 0) ? g_fa : g_fb;

  const int tid  = threadIdx.x;
  const int wid  = tid >> 5;
  const int lane = tid & 31;
  const int v0   = blockIdx.x * 128;
  const int vg   = v0 + tid;

  constexpr int SMAX = (L == 0) ? 2 : 4;
  constexpr int JMAX = (L == 0) ? 4 : 8;

  const uint32_t aRow = (uint32_t)(lane & 15);
  const uint32_t aKb  = (uint32_t)((lane >> 4) * 16);
  const uint32_t bRow = (uint32_t)(lane & 7);
  const uint32_t bKb  = (uint32_t)(((lane >> 3) & 1) * 16);

  const int co = tid >> 1, hh = tid & 1;
  const uint4* wsrc_h = g_Whi + (size_t)L*13824 + (size_t)co*8 + hh*4;
  const uint4 zz = make_uint4(0,0,0,0);

  float acc[2][8][4];
  #pragma unroll
  for (int m = 0; m < 2; ++m)
    #pragma unroll
    for (int n = 0; n < 8; ++n)
      #pragma unroll
      for (int q = 0; q < 4; ++q) acc[m][n][q] = 0.0f;

  uint4 rA[JMAX], rW[4];
  auto loadk = [&](int kk){
    int idx = (vg < N) ? g_nbrT[(size_t)kk*NVOX + vg] : N;
    if (idx < N){
      const uint4* sh = fh + (size_t)idx*8;
      #pragma unroll
      for (int j = 0; j < JMAX; ++j) rA[j] = sh[j];
    } else {
      #pragma unroll
      for (int j = 0; j < JMAX; ++j) rA[j] = zz;
    }
    const uint4* wh = wsrc_h + (size_t)kk*512;
    #pragma unroll
    for (int j = 0; j < 4; ++j) rW[j] = wh[j];
  };

  loadk(0);

  for (int kk = 0; kk < 27; ++kk){
    __syncthreads();   // previous iteration's ldmatrix reads complete; tiles free
    #pragma unroll
    for (int j = 0; j < JMAX; ++j)
      sts128(Ah + SWZ((uint32_t)(tid*128 + j*16)), rA[j]);
    #pragma unroll
    for (int j = 0; j < 4; ++j)
      sts128(Wh + SWZ((uint32_t)(co*128 + hh*64 + j*16)), rW[j]);
    __syncthreads();   // staged data visible to all warps

    if (kk < 26) loadk(kk + 1);   // LDGs overlap the compute below

    #pragma unroll
    for (int s = 0; s < SMAX; ++s){
      uint32_t bhf[8][2];
      #pragma unroll
      for (int n = 0; n < 8; ++n){
        uint32_t bo = SWZ((uint32_t)((n*8 + bRow)*128) + bKb + (uint32_t)(s*32));
        ldmx2(bhf[n], Wh + bo);
      }
      #pragma unroll
      for (int m = 0; m < 2; ++m){
        uint32_t ahf[4];
        uint32_t ao = SWZ((uint32_t)((wid*32 + m*16 + aRow)*128) + aKb + (uint32_t)(s*32));
        ldmx4(ahf, Ah + ao);
        #pragma unroll
        for (int n = 0; n < 8; ++n){
          mma16816(acc[m][n], ahf, bhf[n]);
        }
      }
    }
  }

  // epilogue: bias + relu -> bf16
  float2 bias_[8];
  #pragma unroll
  for (int n = 0; n < 8; ++n){
    int col = n*8 + (lane & 3)*2;
    bias_[n].x = b[col];
    bias_[n].y = b[col + 1];
  }
  __nv_bfloat162* dsth = reinterpret_cast<__nv_bfloat162*>((SRC == 0) ? g_fb : g_fa);

  #pragma unroll
  for (int m = 0; m < 2; ++m){
    #pragma unroll
    for (int h2 = 0; h2 < 2; ++h2){
      int r = v0 + wid*32 + m*16 + (lane >> 2) + h2*8;
      if (r < N){
        size_t ebase = (size_t)r*32 + (lane & 3);
        #pragma unroll
        for (int n = 0; n < 8; ++n){
          float va = relu_(acc[m][n][h2*2 + 0] + bias_[n].x);
          float vb = relu_(acc[m][n][h2*2 + 1] + bias_[n].y);
          __nv_bfloat162 ph;
          ph.x = __float2bfloat16(va);
          ph.y = __float2bfloat16(vb);
          dsth[ebase + n*4] = ph;
        }
      }
    }
  }
}

// ---------------- fused fine stage on tensor cores (validated R14) ----------------
__global__ __launch_bounds__(128) void fine_mma_kernel(
    const int* __restrict__ parent, const int* __restrict__ off,
    const float* __restrict__ bt, const float* __restrict__ bd1,
    const float* __restrict__ bd2,
    const float* __restrict__ xup, float* __restrict__ out)
{
  __shared__ __align__(1024) unsigned char sGr[8192];
  __shared__ __align__(1024) unsigned char sYr[8192];
  __shared__ __align__(1024) unsigned char sWr[8192];
  const uint32_t sG = smem_u32(sGr);
  const uint32_t sY = smem_u32(sYr);
  const uint32_t sW = smem_u32(sWr);

  const int tid = threadIdx.x, w = tid >> 5, lane = tid & 31;
  const int base = blockIdx.x * 64;
  int m0 = g_list[base];
  if (m0 < 0) return;
  const int k = off[m0];

  const uint4 zz = make_uint4(0,0,0,0);

  {
    int r = tid >> 1, half = tid & 1;
    int m = g_list[base + r];
    const uint4* src = (m >= 0) ? (g_fb + (size_t)parent[m]*8 + half*4) : nullptr;
    #pragma unroll
    for (int j = 0; j < 4; ++j){
      uint32_t o = SWZ((uint32_t)(r*128 + half*64 + j*16));
      sts128(sG + o, src ? src[j] : zz);
    }
  }
  {
    const uint4* ws = g_WtT + (size_t)k*512 + (size_t)(tid>>1)*8 + (tid&1)*4;
    #pragma unroll
    for (int j = 0; j < 4; ++j){
      uint32_t o = SWZ((uint32_t)((tid>>1)*128 + (tid&1)*64 + j*16));
      sts128(sW + o, ws[j]);
    }
  }
  __syncthreads();

  const uint32_t aRow = (uint32_t)(lane & 15);
  const uint32_t aKb  = (uint32_t)((lane >> 4) * 16);
  const uint32_t bRow = (uint32_t)(lane & 7);
  const uint32_t bKb  = (uint32_t)(((lane >> 3) & 1) * 16);

  // ---- stage 1: G @ WtT -> sY (relu + bt, bf16) ----
  {
    float acc[8][4];
    #pragma unroll
    for (int n = 0; n < 8; ++n){ acc[n][0]=0; acc[n][1]=0; acc[n][2]=0; acc[n][3]=0; }
    #pragma unroll
    for (int s = 0; s < 4; ++s){
      uint32_t bhf[8][2];
      #pragma unroll
      for (int n = 0; n < 8; ++n){
        uint32_t bo = SWZ((uint32_t)((n*8 + bRow)*128) + bKb + (uint32_t)(s*32));
        ldmx2(bhf[n], sW + bo);
      }
      uint32_t ahf[4];
      uint32_t ao = SWZ((uint32_t)((w*16 + aRow)*128) + aKb + (uint32_t)(s*32));
      ldmx4(ahf, sG + ao);
      #pragma unroll
      for (int n = 0; n < 8; ++n) mma16816(acc[n], ahf, bhf[n]);
    }
    #pragma unroll
    for (int n = 0; n < 8; ++n){
      int col = n*8 + (lane & 3)*2;
      float bx = bt[col], by = bt[col + 1];
      #pragma unroll
      for (int h2 = 0; h2 < 2; ++h2){
        int r = w*16 + (lane >> 2) + h2*8;
        uint32_t o = SWZ((uint32_t)(r*128 + col*2));
        sts32(sY + o, packbf(relu_(acc[n][h2*2] + bx), relu_(acc[n][h2*2+1] + by)));
      }
    }
  }
  __syncthreads();
  {
    const uint4* ws = g_Wd1T + (size_t)(tid>>1)*8 + (tid&1)*4;
    #pragma unroll
    for (int j = 0; j < 4; ++j){
      uint32_t o = SWZ((uint32_t)((tid>>1)*128 + (tid&1)*64 + j*16));
      sts128(sW + o, ws[j]);
    }
  }
  __syncthreads();

  // ---- stage 2: Y @ Wd1T -> sG (relu + bd1, bf16) ----
  {
    float acc[8][4];
    #pragma unroll
    for (int n = 0; n < 8; ++n){ acc[n][0]=0; acc[n][1]=0; acc[n][2]=0; acc[n][3]=0; }
    #pragma unroll
    for (int s = 0; s < 4; ++s){
      uint32_t bhf[8][2];
      #pragma unroll
      for (int n = 0; n < 8; ++n){
        uint32_t bo = SWZ((uint32_t)((n*8 + bRow)*128) + bKb + (uint32_t)(s*32));
        ldmx2(bhf[n], sW + bo);
      }
      uint32_t ahf[4];
      uint32_t ao = SWZ((uint32_t)((w*16 + aRow)*128) + aKb + (uint32_t)(s*32));
      ldmx4(ahf, sY + ao);
      #pragma unroll
      for (int n = 0; n < 8; ++n) mma16816(acc[n], ahf, bhf[n]);
    }
    __syncthreads();
    #pragma unroll
    for (int n = 0; n < 8; ++n){
      int col = n*8 + (lane & 3)*2;
      float bx = bd1[col], by = bd1[col + 1];
      #pragma unroll
      for (int h2 = 0; h2 < 2; ++h2){
        int r = w*16 + (lane >> 2) + h2*8;
        uint32_t o = SWZ((uint32_t)(r*128 + col*2));
        sts32(sG + o, packbf(relu_(acc[n][h2*2] + bx), relu_(acc[n][h2*2+1] + by)));
      }
    }
  }
  __syncthreads();
  {
    int row = tid >> 2, q = tid & 3;
    const uint4* ws = g_Wd2T + (size_t)row*8 + q*2;
    #pragma unroll
    for (int j = 0; j < 2; ++j){
      uint32_t o = SWZ((uint32_t)(row*128 + q*32 + j*16));
      sts128(sW + o, ws[j]);
    }
  }
  __syncthreads();

  // ---- stage 3: Z @ Wd2T + bd2 + xup -> out (fp32) ----
  {
    float acc[4][4];
    #pragma unroll
    for (int n = 0; n < 4; ++n){ acc[n][0]=0; acc[n][1]=0; acc[n][2]=0; acc[n][3]=0; }
    #pragma unroll
    for (int s = 0; s < 4; ++s){
      uint32_t bhf[4][2];
      #pragma unroll
      for (int n = 0; n < 4; ++n){
        uint32_t bo = SWZ((uint32_t)((n*8 + bRow)*128) + bKb + (uint32_t)(s*32));
        ldmx2(bhf[n], sW + bo);
      }
      uint32_t ahf[4];
      uint32_t ao = SWZ((uint32_t)((w*16 + aRow)*128) + aKb + (uint32_t)(s*32));
      ldmx4(ahf, sG + ao);
      #pragma unroll
      for (int n = 0; n < 4; ++n) mma16816(acc[n], ahf, bhf[n]);
    }
    #pragma unroll
    for (int n = 0; n < 4; ++n){
      int col = n*8 + (lane & 3)*2;
      float bx = bd2[col], by = bd2[col + 1];
      #pragma unroll
      for (int h2 = 0; h2 < 2; ++h2){
        int r = w*16 + (lane >> 2) + h2*8;
        int m = g_list[base + r];
        if (m >= 0){
          float2 up = *reinterpret_cast<const float2*>(xup + (size_t)m*32 + col);
          float2 o;
          o.x = acc[n][h2*2 + 0] + bx + up.x;
          o.y = acc[n][h2*2 + 1] + by + up.y;
          *reinterpret_cast<float2*>(out + (size_t)m*32 + col) = o;
        }
      }
    }
  }
}

// -------------------------------- launch --------------------------------
extern "C" void kernel_launch(void* const* d_in, const int* in_sizes, int n_in,
                              void* d_out, int out_size)
{
  const float* feats  = (const float*)d_in[0];
  const float* xup    = (const float*)d_in[1];
  const int*   nbr    = (const int*)  d_in[2];
  const int*   parent = (const int*)  d_in[3];
  const int*   off    = (const int*)  d_in[4];
  const float* We1 = (const float*)d_in[5];  const float* be1 = (const float*)d_in[6];
  const float* We2 = (const float*)d_in[7];  const float* be2 = (const float*)d_in[8];
  const float* We3 = (const float*)d_in[9];  const float* be3 = (const float*)d_in[10];
  const float* Wt  = (const float*)d_in[11]; const float* bt  = (const float*)d_in[12];
  const float* Wd1 = (const float*)d_in[13]; const float* bd1 = (const float*)d_in[14];
  const float* Wd2 = (const float*)d_in[15]; const float* bd2 = (const float*)d_in[16];
  float* out = (float*)d_out;

  // prep
  const int wblk = (27*64*64 + 255)/256;
  prep_w_kernel<32,0><<<wblk, 256>>>(We1);
  prep_w_kernel<64,1><<<wblk, 256>>>(We2);
  prep_w_kernel<64,2><<<wblk, 256>>>(We3);
  prep_wfine_kernel<<<(8*64*64 + 64*64 + 32*64 + 255)/256, 256>>>(Wt, Wd1, Wd2);
  cvt_feats_kernel<<<(NVOX*64 + 255)/256, 256>>>(feats);
  trans_nbr_kernel<<<(27*NVOX + 255)/256, 256>>>(nbr);

  // bucket fine voxels by tconv offset
  init_kernel   <<<(MFINE + 512 + 255)/256, 256>>>();
  count_kernel  <<<(MFINE + 255)/256, 256>>>(off);
  scan_kernel   <<<1, 1>>>();
  scatter_kernel<<<(MFINE + 255)/256, 256>>>(off);

  // encoder: 3 sparse convs on tensor cores (register-pipelined gather)
  const int cblocks = (NVOX + 127)/128;
  conv_mma_kernel<0,0><<<cblocks, 128>>>(be1, NVOX);   // g_fa -> g_fb
  conv_mma_kernel<1,1><<<cblocks, 128>>>(be2, NVOX);   // g_fb -> g_fa
  conv_mma_kernel<2,0><<<cblocks, 128>>>(be3, NVOX);   // g_fa -> g_fb (bf16 for fine)

  // fused fine stage on tensor cores
  fine_mma_kernel<<<(MFINE + 512)/64, 128>>>(parent, off, bt, bd1, bd2, xup, out);
}